// round 4
// baseline (speedup 1.0000x reference)
#include <cuda_runtime.h>
#include <cooperative_groups.h>
#include <cstdint>

namespace cg = cooperative_groups;

#define T_STEPS   32768
#define IN_SIZE   1024
#define HID       512
#define OUT_SIZE  128
#define CLUSTER   8
#define RNN_THREADS 512

// Scratch for the precomputed input projection xb[t][h] (64 MB, allocation-free).
__device__ float g_xb[(size_t)T_STEPS * HID];

// ---- packed fp32x2 helpers (sm_103a FFMA2 — PTX-only, doubles fp32 FMA tput) ----
__device__ __forceinline__ void ffma2(unsigned long long& d,
                                      unsigned long long a,
                                      unsigned long long b) {
    asm("fma.rn.f32x2 %0, %1, %2, %0;" : "+l"(d) : "l"(a), "l"(b));
}
__device__ __forceinline__ unsigned long long pack2(float x, float y) {
    unsigned long long r;
    asm("mov.b64 %0, {%1, %2};" : "=l"(r) : "f"(x), "f"(y));
    return r;
}
__device__ __forceinline__ void unpack2(unsigned long long v, float& x, float& y) {
    asm("mov.b64 {%0, %1}, %2;" : "=f"(x), "=f"(y) : "l"(v));
}

// =====================================================================
// Kernel 1: xb = name @ W1^T + b1   (fp32 SIMT GEMM, NT, FFMA2 microkernel)
//   A = name [T, 1024], B = W1 [512, 1024], C = g_xb [T, 512]
// =====================================================================
#define BM 64
#define BN 64
#define BK 16

__global__ __launch_bounds__(256) void gemm_xb(
    const float* __restrict__ A,
    const float* __restrict__ B,
    const float* __restrict__ b1)
{
    __shared__ __align__(16) float As[BK][BM];
    __shared__ __align__(16) float Bs[BK][BN];

    const int bx  = blockIdx.x;          // over HID (8 blocks)
    const int by  = blockIdx.y;          // over T   (512 blocks)
    const int tid = threadIdx.x;
    const int tx  = tid & 15;            // 0..15 -> 4 output cols each
    const int ty  = tid >> 4;            // 0..15 -> 4 output rows each
    const int lrow = tid >> 2;           // 0..63 load row
    const int lcol = (tid & 3) << 2;     // 0,4,8,12 load col (within BK)

    const float* Ag = A + (size_t)(by * BM + lrow) * IN_SIZE + lcol;
    const float* Bg = B + (size_t)(bx * BN + lrow) * IN_SIZE + lcol;

    unsigned long long acc2[4][2];
    #pragma unroll
    for (int i = 0; i < 4; i++)
        #pragma unroll
        for (int p = 0; p < 2; p++)
            acc2[i][p] = pack2(0.f, 0.f);

    for (int k0 = 0; k0 < IN_SIZE; k0 += BK) {
        float4 av = *(const float4*)(Ag + k0);
        float4 bv = *(const float4*)(Bg + k0);
        As[lcol + 0][lrow] = av.x; As[lcol + 1][lrow] = av.y;
        As[lcol + 2][lrow] = av.z; As[lcol + 3][lrow] = av.w;
        Bs[lcol + 0][lrow] = bv.x; Bs[lcol + 1][lrow] = bv.y;
        Bs[lcol + 2][lrow] = bv.z; Bs[lcol + 3][lrow] = bv.w;
        __syncthreads();

        #pragma unroll
        for (int kk = 0; kk < BK; kk++) {
            float4 a4 = *(const float4*)&As[kk][ty * 4];
            ulonglong2 bp = *(const ulonglong2*)&Bs[kk][tx * 4];
            unsigned long long a0 = pack2(a4.x, a4.x);
            unsigned long long a1 = pack2(a4.y, a4.y);
            unsigned long long a2 = pack2(a4.z, a4.z);
            unsigned long long a3 = pack2(a4.w, a4.w);
            ffma2(acc2[0][0], a0, bp.x); ffma2(acc2[0][1], a0, bp.y);
            ffma2(acc2[1][0], a1, bp.x); ffma2(acc2[1][1], a1, bp.y);
            ffma2(acc2[2][0], a2, bp.x); ffma2(acc2[2][1], a2, bp.y);
            ffma2(acc2[3][0], a3, bp.x); ffma2(acc2[3][1], a3, bp.y);
        }
        __syncthreads();
    }

    const int col = bx * BN + tx * 4;
    float4 bias = *(const float4*)&b1[col];
    #pragma unroll
    for (int i = 0; i < 4; i++) {
        float c0, c1, c2, c3;
        unpack2(acc2[i][0], c0, c1);
        unpack2(acc2[i][1], c2, c3);
        const int row = by * BM + ty * 4 + i;
        float4 o;
        o.x = c0 + bias.x; o.y = c1 + bias.y;
        o.z = c2 + bias.z; o.w = c3 + bias.w;
        *(float4*)&g_xb[(size_t)row * HID + col] = o;
    }
}

// =====================================================================
// Kernel 2: sequential scan, 8-CTA cluster, W2 register-resident.
//   CTA r owns output rows [64r, 64r+64). Thread (g, j): row = 64r+g,
//   K-slice { i*32 + j*4 + c : i<16, c<4 }. h replicated per-CTA in SMEM,
//   double-buffered; per step each thread DSMEM-stores its row's result
//   to CTA j, then one cluster.sync.
// =====================================================================
__global__ void __cluster_dims__(CLUSTER, 1, 1) __launch_bounds__(RNN_THREADS, 1)
rnn_scan(const float* __restrict__ W2, const float* __restrict__ b2,
         const float* __restrict__ W3, const float* __restrict__ b3,
         float* __restrict__ out)
{
    __shared__ __align__(16) float h_buf[2][HID];

    cg::cluster_group cluster = cg::this_cluster();
    const int rank = (int)cluster.block_rank();
    const int tid  = threadIdx.x;
    const int g    = tid >> 3;         // 0..63: row within this CTA's slice
    const int j    = tid & 7;          // 0..7: K slice AND broadcast target rank
    const int row  = rank * 64 + g;    // global hidden row this thread helps compute

    // 64 W2 weights per thread, packed as fp32x2 pairs (32 regs of u64).
    ulonglong2 wl[16];
    #pragma unroll
    for (int i = 0; i < 16; i++)
        wl[i] = *(const ulonglong2*)&W2[(size_t)row * HID + i * 32 + j * 4];

    const float bias = b2[row];

    h_buf[0][tid] = 0.f;
    h_buf[1][tid] = 0.f;
    __syncthreads();
    cluster.sync();   // all CTAs' buffers initialized before any remote store

    // DSMEM base of target CTA j's h_buf.
    float* dst = cluster.map_shared_rank(&h_buf[0][0], j);

    float xcur = g_xb[row];            // xb[0][row], prefetched one step ahead below
    for (int t = 0; t < T_STEPS; t++) {
        const int cur = t & 1;
        const int nxt = cur ^ 1;
        const int tn  = (t + 1 < T_STEPS) ? (t + 1) : (T_STEPS - 1);
        const float xnext = g_xb[(size_t)tn * HID + row];   // prefetch

        unsigned long long acc2 = pack2((j == 0) ? (xcur + bias) : 0.f, 0.f);
        #pragma unroll
        for (int i = 0; i < 16; i++) {
            ulonglong2 hv = *(const ulonglong2*)&h_buf[cur][i * 32 + j * 4];
            ffma2(acc2, wl[i].x, hv.x);
            ffma2(acc2, wl[i].y, hv.y);
        }
        float alo, ahi;
        unpack2(acc2, alo, ahi);
        float acc = alo + ahi;
        // reduce the 8-thread group (lane-aligned within the warp)
        acc += __shfl_xor_sync(0xFFFFFFFFu, acc, 4);
        acc += __shfl_xor_sync(0xFFFFFFFFu, acc, 2);
        acc += __shfl_xor_sync(0xFFFFFFFFu, acc, 1);

        // tanh: exact to ~1e-7 abs: (e^{2x}-1)/(e^{2x}+1), clamped
        float xc = fminf(fmaxf(acc, -10.f), 10.f);
        float e  = __expf(2.f * xc);
        float hnew = __fdividef(e - 1.f, e + 1.f);

        // broadcast: thread (row, j) writes h_new[row] into CTA j's next buffer
        dst[nxt * HID + row] = hnew;
        xcur = xnext;
        cluster.sync();                // release stores, acquire for next step
    }

    // Final projection (h_final sits in h_buf[0] of every CTA; T is even).
    if (rank == 0 && tid < OUT_SIZE) {
        float s = b3[tid];
        #pragma unroll 8
        for (int k = 0; k < HID; k += 4) {
            float4 w = *(const float4*)&W3[(size_t)tid * HID + k];
            s = fmaf(w.x, h_buf[0][k + 0], s);
            s = fmaf(w.y, h_buf[0][k + 1], s);
            s = fmaf(w.z, h_buf[0][k + 2], s);
            s = fmaf(w.w, h_buf[0][k + 3], s);
        }
        out[tid] = s;
    }
}

// =====================================================================
extern "C" void kernel_launch(void* const* d_in, const int* in_sizes, int n_in,
                              void* d_out, int out_size) {
    const float* name = (const float*)d_in[0];
    const float* W1   = (const float*)d_in[1];
    const float* b1   = (const float*)d_in[2];
    const float* W2   = (const float*)d_in[3];
    const float* b2   = (const float*)d_in[4];
    const float* W3   = (const float*)d_in[5];
    const float* b3   = (const float*)d_in[6];
    float* out = (float*)d_out;

    gemm_xb<<<dim3(HID / BN, T_STEPS / BM), 256>>>(name, W1, b1);
    rnn_scan<<<CLUSTER, RNN_THREADS>>>(W2, b2, W3, b3, out);
}

// round 5
// speedup vs baseline: 1.9837x; 1.9837x over previous
#include <cuda_runtime.h>
#include <cstdint>

#define T_STEPS   32768
#define IN_SIZE   1024
#define HID       512
#define OUT_SIZE  128

// Scratch for the precomputed input projection xb[t][h] (64 MB, allocation-free).
__device__ float g_xb[(size_t)T_STEPS * HID];

// ---- packed fp32x2 helpers (sm_103a FFMA2/FADD2 — PTX-only) ----
__device__ __forceinline__ void ffma2(unsigned long long& d,
                                      unsigned long long a,
                                      unsigned long long b) {
    asm("fma.rn.f32x2 %0, %1, %2, %0;" : "+l"(d) : "l"(a), "l"(b));
}
__device__ __forceinline__ unsigned long long addf2(unsigned long long a,
                                                    unsigned long long b) {
    unsigned long long r;
    asm("add.rn.f32x2 %0, %1, %2;" : "=l"(r) : "l"(a), "l"(b));
    return r;
}
__device__ __forceinline__ unsigned long long pack2(float x, float y) {
    unsigned long long r;
    asm("mov.b64 %0, {%1, %2};" : "=l"(r) : "f"(x), "f"(y));
    return r;
}
__device__ __forceinline__ void unpack2(unsigned long long v, float& x, float& y) {
    asm("mov.b64 {%0, %1}, %2;" : "=f"(x), "=f"(y) : "l"(v));
}

// ---- cluster / mbarrier / st.async primitives ----
__device__ __forceinline__ uint32_t su32(const void* p) {
    uint32_t a;
    asm("{ .reg .u64 t; cvta.to.shared.u64 t, %1; cvt.u32.u64 %0, t; }"
        : "=r"(a) : "l"(p));
    return a;
}
__device__ __forceinline__ uint32_t mapa_u32(uint32_t a, uint32_t rank) {
    uint32_t r;
    asm("mapa.shared::cluster.u32 %0, %1, %2;" : "=r"(r) : "r"(a), "r"(rank));
    return r;
}
__device__ __forceinline__ void st_async_b32(uint32_t raddr, uint32_t bits, uint32_t rmbar) {
    asm volatile("st.async.shared::cluster.mbarrier::complete_tx::bytes.b32 [%0], %1, [%2];"
                 :: "r"(raddr), "r"(bits), "r"(rmbar) : "memory");
}
__device__ __forceinline__ void mbar_init(uint32_t m, uint32_t c) {
    asm volatile("mbarrier.init.shared.b64 [%0], %1;" :: "r"(m), "r"(c) : "memory");
}
__device__ __forceinline__ void mbar_arrive(uint32_t m) {
    asm volatile("mbarrier.arrive.shared.b64 _, [%0];" :: "r"(m) : "memory");
}
__device__ __forceinline__ void mbar_expect(uint32_t m, uint32_t tx) {
    asm volatile("mbarrier.arrive.expect_tx.shared.b64 _, [%0], %1;"
                 :: "r"(m), "r"(tx) : "memory");
}
__device__ __forceinline__ void mbar_wait_acq_cluster(uint32_t m, uint32_t parity) {
    asm volatile(
        "{\n\t"
        ".reg .pred P;\n"
        "LWAIT%=:\n\t"
        "mbarrier.try_wait.parity.acquire.cluster.shared::cta.b64 P, [%0], %1, 0x989680;\n\t"
        "@!P bra LWAIT%=;\n\t"
        "}"
        :: "r"(m), "r"(parity) : "memory");
}

// =====================================================================
// Kernel 1: xb = name @ W1^T + b1   (fp32 SIMT GEMM, NT, FFMA2 microkernel)
// =====================================================================
#define BM 64
#define BN 64
#define BK 16

__global__ __launch_bounds__(256) void gemm_xb(
    const float* __restrict__ A,
    const float* __restrict__ B,
    const float* __restrict__ b1)
{
    __shared__ __align__(16) float As[BK][BM];
    __shared__ __align__(16) float Bs[BK][BN];

    const int bx  = blockIdx.x;
    const int by  = blockIdx.y;
    const int tid = threadIdx.x;
    const int tx  = tid & 15;
    const int ty  = tid >> 4;
    const int lrow = tid >> 2;
    const int lcol = (tid & 3) << 2;

    const float* Ag = A + (size_t)(by * BM + lrow) * IN_SIZE + lcol;
    const float* Bg = B + (size_t)(bx * BN + lrow) * IN_SIZE + lcol;

    unsigned long long acc2[4][2];
    #pragma unroll
    for (int i = 0; i < 4; i++)
        #pragma unroll
        for (int p = 0; p < 2; p++)
            acc2[i][p] = pack2(0.f, 0.f);

    for (int k0 = 0; k0 < IN_SIZE; k0 += BK) {
        float4 av = *(const float4*)(Ag + k0);
        float4 bv = *(const float4*)(Bg + k0);
        As[lcol + 0][lrow] = av.x; As[lcol + 1][lrow] = av.y;
        As[lcol + 2][lrow] = av.z; As[lcol + 3][lrow] = av.w;
        Bs[lcol + 0][lrow] = bv.x; Bs[lcol + 1][lrow] = bv.y;
        Bs[lcol + 2][lrow] = bv.z; Bs[lcol + 3][lrow] = bv.w;
        __syncthreads();

        #pragma unroll
        for (int kk = 0; kk < BK; kk++) {
            float4 a4 = *(const float4*)&As[kk][ty * 4];
            ulonglong2 bp = *(const ulonglong2*)&Bs[kk][tx * 4];
            unsigned long long a0 = pack2(a4.x, a4.x);
            unsigned long long a1 = pack2(a4.y, a4.y);
            unsigned long long a2 = pack2(a4.z, a4.z);
            unsigned long long a3 = pack2(a4.w, a4.w);
            ffma2(acc2[0][0], a0, bp.x); ffma2(acc2[0][1], a0, bp.y);
            ffma2(acc2[1][0], a1, bp.x); ffma2(acc2[1][1], a1, bp.y);
            ffma2(acc2[2][0], a2, bp.x); ffma2(acc2[2][1], a2, bp.y);
            ffma2(acc2[3][0], a3, bp.x); ffma2(acc2[3][1], a3, bp.y);
        }
        __syncthreads();
    }

    const int col = bx * BN + tx * 4;
    float4 bias = *(const float4*)&b1[col];
    #pragma unroll
    for (int i = 0; i < 4; i++) {
        float c0, c1, c2, c3;
        unpack2(acc2[i][0], c0, c1);
        unpack2(acc2[i][1], c2, c3);
        const int row = by * BM + ty * 4 + i;
        float4 o;
        o.x = c0 + bias.x; o.y = c1 + bias.y;
        o.z = c2 + bias.z; o.w = c3 + bias.w;
        *(float4*)&g_xb[(size_t)row * HID + col] = o;
    }
}

// =====================================================================
// Kernel 2: sequential scan over CN-CTA cluster, mbarrier/st.async sync.
//   CTA r owns R=HID/CN rows. TPR=NT/R threads per row (==8 in both
//   configs), each covering a 64-column K-slice held in registers.
//   h replicated per-CTA, 4-deep ring buffer h_buf[4][HID]; per step each
//   row group st.asyncs its value into every CTA's next buffer; the
//   receiving mbarrier expects 512 * 4B of tx per phase.
// =====================================================================
template<int CN, int NT>
__global__ __launch_bounds__(NT, 1) void rnn_scan_k(
    const float* __restrict__ W2, const float* __restrict__ b2,
    const float* __restrict__ W3, const float* __restrict__ b3,
    float* __restrict__ out)
{
    constexpr int R    = HID / CN;        // rows per CTA
    constexpr int TPR  = NT / R;          // threads per row (8)
    constexpr int NTGT = CN / TPR;        // st.async targets per thread
    constexpr int NI   = HID / (TPR * 4); // 16 ulonglong2 weight chunks
    constexpr uint32_t TXB = HID * 4;     // 2048 tx bytes per phase

    __shared__ __align__(16) float    h_buf[4][HID];
    __shared__ __align__(8)  uint64_t mbar[4];

    const int tid = threadIdx.x;
    const int j   = tid % TPR;
    const int g   = tid / TPR;
    uint32_t rank; asm("mov.u32 %0, %%cluster_ctarank;" : "=r"(rank));
    const int row = (int)rank * R + g;

    // W2 slice: 64 floats per thread, register-resident as fp32x2 pairs.
    ulonglong2 wl[NI];
    #pragma unroll
    for (int i = 0; i < NI; i++)
        wl[i] = *(const ulonglong2*)&W2[(size_t)row * HID + i * (TPR * 4) + j * 4];
    const float bias = b2[row];

    // Init h0 = 0 and mbarriers.
    for (int i = tid; i < HID; i += NT) h_buf[0][i] = 0.f;
    uint32_t mb[4];
    #pragma unroll
    for (int b = 0; b < 4; b++) mb[b] = su32(&mbar[b]);
    if (tid == 0) {
        #pragma unroll
        for (int b = 0; b < 4; b++) mbar_init(mb[b], 1);
        mbar_arrive(mb[0]);   // pre-complete mbar[0] phase 0 (t=0 has no wait)
    }
    __syncthreads();
    asm volatile("barrier.cluster.arrive.aligned;" ::: "memory");
    asm volatile("barrier.cluster.wait.aligned;"   ::: "memory");

    // Precompute remote addresses (cluster-window) for all 4 buffers.
    uint32_t ra[4][NTGT], rm[4][NTGT];
    #pragma unroll
    for (int b = 0; b < 4; b++) {
        uint32_t lh = su32(&h_buf[b][row]);
        #pragma unroll
        for (int s = 0; s < NTGT; s++) {
            uint32_t tgt = (uint32_t)(j + s * TPR);
            ra[b][s] = mapa_u32(lh, tgt);
            rm[b][s] = mapa_u32(mb[b], tgt);
        }
    }

    float xcur = g_xb[row];   // xb[0][row]
    #pragma unroll 4
    for (int t = 0; t < T_STEPS; t++) {
        const int rb = t & 3;
        const int wb = (t + 1) & 3;
        const uint32_t par = (uint32_t)(t >> 2) & 1u;

        // Prefetch next step's xb before blocking.
        const int tn = (t + 1) & (T_STEPS - 1);
        const float xnext = g_xb[(size_t)tn * HID + row];

        // Arm the next phase's tx expectation, then wait for this step's h.
        if (tid == 0) mbar_expect(mb[wb], TXB);
        if (t != 0)   mbar_wait_acq_cluster(mb[rb], par);

        // Partial dot: 64 cols, 32 FFMA2 into 4 independent f32x2 accums.
        unsigned long long a0 = pack2(0.f, 0.f), a1 = a0, a2 = a0, a3 = a0;
        #pragma unroll
        for (int i = 0; i < NI; i++) {
            ulonglong2 hv = *(const ulonglong2*)&h_buf[rb][i * (TPR * 4) + j * 4];
            if (i & 1) { ffma2(a2, wl[i].x, hv.x); ffma2(a3, wl[i].y, hv.y); }
            else       { ffma2(a0, wl[i].x, hv.x); ffma2(a1, wl[i].y, hv.y); }
        }
        a0 = addf2(a0, a2);
        a1 = addf2(a1, a3);
        a0 = addf2(a0, a1);
        float lo, hi; unpack2(a0, lo, hi);
        float v = lo + hi;
        v += __shfl_xor_sync(0xFFFFFFFFu, v, 4);
        v += __shfl_xor_sync(0xFFFFFFFFu, v, 2);
        v += __shfl_xor_sync(0xFFFFFFFFu, v, 1);

        v += xcur + bias;
        float xc = fminf(fmaxf(v, -10.f), 10.f);
        float e  = __expf(2.f * xc);
        float hnew = __fdividef(e - 1.f, e + 1.f);

        // Deliver h_new[row] to every CTA's next buffer (tx-counted stores).
        const uint32_t bits = __float_as_uint(hnew);
        #pragma unroll
        for (int s = 0; s < NTGT; s++)
            st_async_b32(ra[wb][s], bits, rm[wb][s]);

        xcur = xnext;
    }

    // Consume the final stores (T % 4 == 0 -> buffer 0, parity (T>>2)&1 == 0).
    mbar_wait_acq_cluster(mb[T_STEPS & 3], (uint32_t)(T_STEPS >> 2) & 1u);

    // Final projection from local full h.
    if (rank == 0 && tid < OUT_SIZE) {
        float s = b3[tid];
        #pragma unroll 8
        for (int k = 0; k < HID; k += 4) {
            float4 w = *(const float4*)&W3[(size_t)tid * HID + k];
            s = fmaf(w.x, h_buf[T_STEPS & 3][k + 0], s);
            s = fmaf(w.y, h_buf[T_STEPS & 3][k + 1], s);
            s = fmaf(w.z, h_buf[T_STEPS & 3][k + 2], s);
            s = fmaf(w.w, h_buf[T_STEPS & 3][k + 3], s);
        }
        out[tid] = s;
    }
}

// =====================================================================
extern "C" void kernel_launch(void* const* d_in, const int* in_sizes, int n_in,
                              void* d_out, int out_size) {
    const float* name = (const float*)d_in[0];
    const float* W1   = (const float*)d_in[1];
    const float* b1   = (const float*)d_in[2];
    const float* W2   = (const float*)d_in[3];
    const float* b2   = (const float*)d_in[4];
    const float* W3   = (const float*)d_in[5];
    const float* b3   = (const float*)d_in[6];
    float* out = (float*)d_out;

    gemm_xb<<<dim3(HID / BN, T_STEPS / BM), 256>>>(name, W1, b1);

    cudaLaunchAttribute attr[1];
    attr[0].id = cudaLaunchAttributeClusterDimension;

    // Prefer a 16-CTA cluster (non-portable size); verify launchability and
    // fall back to the portable 8-CTA config otherwise. Pure host-side
    // queries — deterministic and legal during graph capture.
    bool use16 = false;
    if (cudaFuncSetAttribute(rnn_scan_k<16, 256>,
                             cudaFuncAttributeNonPortableClusterSizeAllowed, 1)
        == cudaSuccess) {
        cudaLaunchConfig_t q = {};
        q.gridDim  = dim3(16, 1, 1);
        q.blockDim = dim3(256, 1, 1);
        attr[0].val.clusterDim.x = 16;
        attr[0].val.clusterDim.y = 1;
        attr[0].val.clusterDim.z = 1;
        q.attrs = attr; q.numAttrs = 1;
        int nc = 0;
        if (cudaOccupancyMaxActiveClusters(&nc, rnn_scan_k<16, 256>, &q)
                == cudaSuccess && nc >= 1)
            use16 = true;
    }

    if (use16) {
        cudaLaunchConfig_t cfg = {};
        cfg.gridDim  = dim3(16, 1, 1);
        cfg.blockDim = dim3(256, 1, 1);
        attr[0].val.clusterDim.x = 16;
        attr[0].val.clusterDim.y = 1;
        attr[0].val.clusterDim.z = 1;
        cfg.attrs = attr; cfg.numAttrs = 1;
        cudaLaunchKernelEx(&cfg, rnn_scan_k<16, 256>, W2, b2, W3, b3, out);
    } else {
        cudaLaunchConfig_t cfg = {};
        cfg.gridDim  = dim3(8, 1, 1);
        cfg.blockDim = dim3(512, 1, 1);
        attr[0].val.clusterDim.x = 8;
        attr[0].val.clusterDim.y = 1;
        attr[0].val.clusterDim.z = 1;
        cfg.attrs = attr; cfg.numAttrs = 1;
        cudaLaunchKernelEx(&cfg, rnn_scan_k<8, 512>, W2, b2, W3, b3, out);
    }
}